// round 7
// baseline (speedup 1.0000x reference)
#include <cuda_runtime.h>
#include <cstddef>

// pred_raw[b, 4h+i, 4w+j] = y[b, C[k], 4h+RO[k], 4w+CO[k]], k = 4*i+j.
// Packed per-class delta = (C<<20) | (RO<<10) | CO  (k=15 duplicates k=3).
// Block = one full output row (b, H): phase i = H&3 uniform per block ->
// exactly 5 DRAM streams per block (1 x row + 4 y rows) for HBM page locality.
__constant__ int kDelta[16] = {
    (0<<20)|(0<<10)|0,  (3<<20)|(0<<10)|1,  (1<<20)|(0<<10)|2,  (4<<20)|(0<<10)|3,
    (6<<20)|(1<<10)|0,  (9<<20)|(1<<10)|1,  (7<<20)|(1<<10)|2, (10<<20)|(1<<10)|3,
    (1<<20)|(2<<10)|0,  (4<<20)|(2<<10)|1,  (8<<20)|(3<<10)|0, (10<<20)|(3<<10)|1,
    (2<<20)|(2<<10)|2,  (5<<20)|(2<<10)|3,  (9<<20)|(3<<10)|2,  (4<<20)|(0<<10)|3
};

#define NB      8192           // 8 batches * 1024 output rows
#define N_TOTAL 8388608.0f

__device__ float        g_partials[NB];
__device__ unsigned int g_done = 0;

__global__ void __launch_bounds__(256)
loss_fused(const float* __restrict__ x, const float* __restrict__ y,
           float* __restrict__ out)
{
    const int tid  = threadIdx.x;      // quad column wq
    const int lane = tid & 31;
    const int warp = tid >> 5;
    const int g    = blockIdx.x;
    const int H    = g & 1023;         // output row
    const int b    = g >> 10;          // batch
    const int i    = H & 3;
    const int h    = H >> 2;

    // x: one fully-coalesced float4 per thread (block covers the whole row)
    const float4 xv = *reinterpret_cast<const float4*>(
        x + ((((size_t)b << 10) + H) << 10) + (tid << 2));

    // y: 4 independent scalar loads; deltas uniform per block (i uniform)
    const size_t ybase = (((size_t)(b * 12)) << 20)
                       + (((size_t)(h << 2)) << 10) + (tid << 2);
    const int kb = i << 2;
    const float y0 = y[ybase + kDelta[kb + 0]];
    const float y1 = y[ybase + kDelta[kb + 1]];
    const float y2 = y[ybase + kDelta[kb + 2]];
    const float y3 = y[ybase + kDelta[kb + 3]];

    float s = fabsf(y0 - xv.x) + fabsf(y1 - xv.y)
            + fabsf(y2 - xv.z) + fabsf(y3 - xv.w);

    // ---- deterministic block reduction ----
    #pragma unroll
    for (int m = 16; m > 0; m >>= 1)
        s += __shfl_xor_sync(0xFFFFFFFFu, s, m);

    __shared__ float sm[8];
    __shared__ bool  s_last;
    if (lane == 0) sm[warp] = s;
    __syncthreads();
    if (tid == 0) {
        float v = 0.0f;
        #pragma unroll
        for (int w = 0; w < 8; w++) v += sm[w];
        g_partials[g] = v;
        __threadfence();
        unsigned int prev = atomicAdd(&g_done, 1u);
        s_last = (prev == NB - 1);
    }
    __syncthreads();

    // ---- last block: fixed-order final sum (deterministic) ----
    if (s_last) {
        float t = 0.0f;
        #pragma unroll 8
        for (int idx = tid; idx < NB; idx += 256)
            t += g_partials[idx];
        #pragma unroll
        for (int m = 16; m > 0; m >>= 1)
            t += __shfl_xor_sync(0xFFFFFFFFu, t, m);
        if (lane == 0) sm[warp] = t;
        __syncthreads();
        if (tid == 0) {
            float v = 0.0f;
            #pragma unroll
            for (int w = 0; w < 8; w++) v += sm[w];
            out[0] = v * (1.0f / N_TOTAL);
            g_done = 0;                  // reset for next graph replay
        }
    }
}

extern "C" void kernel_launch(void* const* d_in, const int* in_sizes, int n_in,
                              void* d_out, int out_size) {
    const float* x;
    const float* y;
    if (in_sizes[0] == 8 * 1024 * 1024) {
        x = (const float*)d_in[0];
        y = (const float*)d_in[1];
    } else {
        x = (const float*)d_in[1];
        y = (const float*)d_in[0];
    }
    loss_fused<<<NB, 256>>>(x, y, (float*)d_out);
}

// round 8
// speedup vs baseline: 1.2225x; 1.2225x over previous
#include <cuda_runtime.h>
#include <cstddef>

// pred_raw[b, 4h+i, 4w+j] = y[b, C[k], 4h+RO[k], 4w+CO[k]], k = 4*i+j.
// Block = 8 consecutive output rows (rows 8r..8r+7): per unrolled iteration u,
// i = u&3 is compile-time -> all y offsets are immediates; exactly 5 DRAM
// row-streams active per iteration (1 x row + 4 y rows).
// k=15 duplicates k=3 (affects only i=3 row's j=3 element).

#define NB      1024           // 8 batches * 128 row-groups
#define N_TOTAL 8388608.0f

__device__ float        g_partials[NB];
__device__ unsigned int g_done = 0;

__global__ void __launch_bounds__(256)
loss_fused(const float* __restrict__ x, const float* __restrict__ y,
           float* __restrict__ out)
{
    const int tid  = threadIdx.x;      // quad column
    const int lane = tid & 31;
    const int warp = tid >> 5;
    const int g    = blockIdx.x;
    const int b    = g >> 7;           // batch
    const int r    = g & 127;          // row-group: output rows 8r..8r+7

    const int kC[16]  = {0,3,1,4, 6,9,7,10, 1,4,8,10, 2,5,9,4};
    const int kRO[16] = {0,0,0,0, 1,1,1,1,  2,2,3,3,  2,2,3,0};
    const int kCO[16] = {0,1,2,3, 0,1,2,3,  0,1,0,1,  2,3,2,3};

    float s0 = 0.0f, s1 = 0.0f;

    #pragma unroll
    for (int u = 0; u < 8; u++) {
        const int H = (r << 3) + u;            // output row (compile-time split)
        const int i = u & 3;                   // compile-time per iteration
        const int kb = i << 2;

        // x: one fully-coalesced float4 (block covers full row)
        const float4 xv = *reinterpret_cast<const float4*>(
            x + ((((size_t)b << 10) + H) << 10) + (tid << 2));

        // y: 4 independent scalar loads, immediate class offsets
        const size_t ybase = (((size_t)(b * 12)) << 20)
                           + (((size_t)(H & ~3)) << 10) + (tid << 2);
        const float y0 = y[ybase + ((size_t)kC[kb+0] << 20) + (kRO[kb+0] << 10) + kCO[kb+0]];
        const float y1 = y[ybase + ((size_t)kC[kb+1] << 20) + (kRO[kb+1] << 10) + kCO[kb+1]];
        const float y2 = y[ybase + ((size_t)kC[kb+2] << 20) + (kRO[kb+2] << 10) + kCO[kb+2]];
        const float y3 = y[ybase + ((size_t)kC[kb+3] << 20) + (kRO[kb+3] << 10) + kCO[kb+3]];

        s0 += fabsf(y0 - xv.x) + fabsf(y2 - xv.z);
        s1 += fabsf(y1 - xv.y) + fabsf(y3 - xv.w);
    }
    float s = s0 + s1;

    // ---- deterministic block reduction ----
    #pragma unroll
    for (int m = 16; m > 0; m >>= 1)
        s += __shfl_xor_sync(0xFFFFFFFFu, s, m);

    __shared__ float sm[8];
    __shared__ bool  s_last;
    if (lane == 0) sm[warp] = s;
    __syncthreads();
    if (tid == 0) {
        float v = 0.0f;
        #pragma unroll
        for (int w = 0; w < 8; w++) v += sm[w];
        g_partials[g] = v;
        __threadfence();
        unsigned int prev = atomicAdd(&g_done, 1u);
        s_last = (prev == NB - 1);
    }
    __syncthreads();

    // ---- last block: fixed-order final sum (deterministic) ----
    if (s_last) {
        float t = 0.0f;
        #pragma unroll 4
        for (int idx = tid; idx < NB; idx += 256)
            t += g_partials[idx];
        #pragma unroll
        for (int m = 16; m > 0; m >>= 1)
            t += __shfl_xor_sync(0xFFFFFFFFu, t, m);
        if (lane == 0) sm[warp] = t;
        __syncthreads();
        if (tid == 0) {
            float v = 0.0f;
            #pragma unroll
            for (int w = 0; w < 8; w++) v += sm[w];
            out[0] = v * (1.0f / N_TOTAL);
            g_done = 0;                  // reset for next graph replay
        }
    }
}

extern "C" void kernel_launch(void* const* d_in, const int* in_sizes, int n_in,
                              void* d_out, int out_size) {
    const float* x;
    const float* y;
    if (in_sizes[0] == 8 * 1024 * 1024) {
        x = (const float*)d_in[0];
        y = (const float*)d_in[1];
    } else {
        x = (const float*)d_in[1];
        y = (const float*)d_in[0];
    }
    loss_fused<<<NB, 256>>>(x, y, (float*)d_out);
}